// round 10
// baseline (speedup 1.0000x reference)
#include <cuda_runtime.h>
#include <math.h>

#define N    2048
#define K    128
#define NMAX 40
#define NB   136
#define NTHR 512

#define SQL2E 1.2011224087864498f
#define NL2E  -0.7213475204444817f
#define HL2E  0.7213475204444817f
#define LN2f  0.6931471805599453f

typedef unsigned long long ull;

__device__ float g_u  [N * K];
__device__ float g_xs [N * K];
__device__ float g_rh [N];
__device__ float g_S  [N];
__device__ float g_T  [NMAX * K];
__device__ float g_pS [128 * K];
__device__ float g_pQ [128 * K];
__device__ float g_acc;
__device__ unsigned g_bar[4];     // zero-init, monotonic epochs (replay-safe)

__constant__ float c_rinv[NMAX] = {
    1.f/1,1.f/2,1.f/3,1.f/4,1.f/5,1.f/6,1.f/7,1.f/8,1.f/9,1.f/10,
    1.f/11,1.f/12,1.f/13,1.f/14,1.f/15,1.f/16,1.f/17,1.f/18,1.f/19,1.f/20,
    1.f/21,1.f/22,1.f/23,1.f/24,1.f/25,1.f/26,1.f/27,1.f/28,1.f/29,1.f/30,
    1.f/31,1.f/32,1.f/33,1.f/34,1.f/35,1.f/36,1.f/37,1.f/38,1.f/39,1.f/40 };

__device__ __forceinline__ float ex2f(float x) {
    float r; asm("ex2.approx.f32 %0, %1;" : "=f"(r) : "f"(x)); return r;
}
__device__ __forceinline__ float lg2f(float x) {
    float r; asm("lg2.approx.f32 %0, %1;" : "=f"(r) : "f"(x)); return r;
}
__device__ __forceinline__ float lnf(float x) { return lg2f(x) * LN2f; }

__device__ __forceinline__ ull splat2(float x) {
    ull r; asm("mov.b64 %0, {%1, %1};" : "=l"(r) : "f"(x)); return r;
}
__device__ __forceinline__ ull pack2(float lo, float hi) {
    ull r; asm("mov.b64 %0, {%1, %2};" : "=l"(r) : "f"(lo), "f"(hi)); return r;
}
__device__ __forceinline__ ull fma2(ull a, ull b, ull c) {
    ull d; asm("fma.rn.f32x2 %0, %1, %2, %3;" : "=l"(d) : "l"(a), "l"(b), "l"(c)); return d;
}
__device__ __forceinline__ void unpack2(ull v, float& lo, float& hi) {
    asm("mov.b64 {%0, %1}, %2;" : "=f"(lo), "=f"(hi) : "l"(v));
}

__device__ __forceinline__ void grid_bar(int b) {
    __syncthreads();
    if (threadIdx.x == 0) {
        __threadfence();
        unsigned ticket = atomicAdd(&g_bar[b], 1u);
        unsigned target = (ticket / NB + 1u) * NB;
        unsigned v;
        do {
            asm volatile("ld.global.acquire.gpu.u32 %0, [%1];"
                         : "=r"(v) : "l"(&g_bar[b]));
        } while (v < target);
    }
    __syncthreads();
}

__global__ __launch_bounds__(NTHR, 1) void fused_kernel(
        const float* __restrict__ z, float* __restrict__ out) {
    __shared__ __align__(16) char s_buf[42240];
    const int tid = threadIdx.x;
    const int B = blockIdx.x;

    // =========== P0: partial column sums (tid<128) + zeroing (tid>=128) ====
    float vals[16];
    if (B < 128 && tid < 128) {
        const int k = tid;
        const int r0 = B * 16;
        float s = 0.f, sq = 0.f;
#pragma unroll
        for (int r = 0; r < 16; r++) {
            float v = z[(r0 + r) * K + k];
            vals[r] = v; s += v; sq += v * v;
        }
        g_pS[B * K + k] = s;
        g_pQ[B * K + k] = sq;
    } else if (tid >= 128) {
        int idx = B * 384 + (tid - 128);
        if (idx < NMAX * K) g_T[idx] = 0.f;
        else if (idx < NMAX * K + N) g_S[idx - NMAX * K] = 0.f;
        if (B == 0 && tid == 128) g_acc = 0.f;
    }
    grid_bar(0);

    // =========== P1: stats finalize + standardize + moments + row norms ====
    if (B < 128) {
        float* mrs   = reinterpret_cast<float*>(s_buf);          // [256]
        float* xs_sh = mrs + 256;                                // [16*128]
        float* shr   = xs_sh + 16 * 128;                         // [16*4]

        const int k = tid & 127;
        const int g = tid >> 7;
        const int r0 = B * 16;

        if (tid < 128) {
            float s = 0.f, sq = 0.f;
#pragma unroll 8
            for (int b = 0; b < 128; b++) {
                s  += g_pS[b * K + k];
                sq += g_pQ[b * K + k];
            }
            float mean = s / (float)N;
            float var = (sq - s * mean) / (float)(N - 1);
            var = fmaxf(var, 0.f);
            float rs = 1.f / (sqrtf(var) + 1e-6f);
            mrs[k] = mean; mrs[128 + k] = rs;
            // group 0 standardizes all 16 rows, stages to smem + global
#pragma unroll
            for (int r = 0; r < 16; r++) {
                float xs = (vals[r] - mean) * rs;
                xs_sh[r * 128 + k] = xs;
                g_xs[(r0 + r) * K + k] = xs;
                g_u [(r0 + r) * K + k] = xs * SQL2E;
            }
        }
        __syncthreads();

        float bx[16], q[16];
#pragma unroll
        for (int r = 0; r < 16; r++) {
            float xs = xs_sh[r * 128 + k];
            bx[r] = xs;
            q[r]  = ex2f(NL2E * xs * xs);
        }

        // moment chains: all groups run full recurrence; group g accumulates
        // only its 10-wide n-range -> 128 atomic writers per g_T address.
        float acc[10];
#pragma unroll
        for (int s = 0; s < 10; s++) acc[s] = 0.f;
#pragma unroll 1
        for (int seg = 0; seg < 4; seg++) {
            const bool mine = (seg == g);
#pragma unroll
            for (int s = 0; s < 10; s++) {
                const float rinv = c_rinv[seg * 10 + s];
#pragma unroll
                for (int r = 0; r < 16; r++) {
                    if (mine) acc[s] += q[r];
                    q[r] *= bx[r] * rinv;
                }
            }
        }
#pragma unroll
        for (int s = 0; s < 10; s++)
            atomicAdd(&g_T[(g * 10 + s) * K + k], acc[s]);

        // row norms: group g reduces rows [4g, 4g+4)
        float rh4[4];
#pragma unroll
        for (int r = 0; r < 4; r++) {
            float v = bx[g * 4 + r];
            rh4[r] = v * v;
        }
#pragma unroll
        for (int o = 16; o; o >>= 1)
#pragma unroll
            for (int r = 0; r < 4; r++)
                rh4[r] += __shfl_xor_sync(0xffffffffu, rh4[r], o);
        const int w = tid >> 5, lane = tid & 31;
        if (lane == 0) {
#pragma unroll
            for (int r = 0; r < 4; r++) shr[w * 4 + r] = rh4[r];
        }
        __syncthreads();
        if (tid < 16) {
            int gg = tid >> 2, rr = tid & 3;
            float tot = shr[(gg * 4 + 0) * 4 + rr] + shr[(gg * 4 + 1) * 4 + rr]
                      + shr[(gg * 4 + 2) * 4 + rr] + shr[(gg * 4 + 3) * 4 + rr];
            g_rh[r0 + tid] = HL2E * tot;
        }
    }
    grid_bar(1);

    // =========== P2: Gram (f32x2) + fused exp + row/col sums ===============
    {
        float (*As)[132] = reinterpret_cast<float(*)[132]>(s_buf);
        float (*Bs)[132] = reinterpret_cast<float(*)[132]>(s_buf + 16896);

        const int tx = tid & 15;       // 8-col group
        const int ty = tid >> 4;       // 0..31, 4-row group

        int rem = B, ti = 0;
        for (int t = 0; t < 16; t++) {
            int L = 16 - t;
            if (rem < L) { ti = t; break; }
            rem -= L;
        }
        const int tj = ti + rem;
        const int i0 = ti * 128, j0 = tj * 128;

        ull acc2[4][4];
#pragma unroll
        for (int m = 0; m < 4; m++)
#pragma unroll
            for (int p = 0; p < 4; p++) acc2[m][p] = splat2(0.f);

#pragma unroll 1
        for (int kc = 0; kc < K; kc += 32) {
            __syncthreads();
#pragma unroll
            for (int r = 0; r < 2; r++) {
                int f = tid + NTHR * r;
                int row = f >> 3, kp = (f & 7) * 4;
                float4 va = *(const float4*)&g_u[(i0 + row) * K + kc + kp];
                As[kp + 0][row] = va.x; As[kp + 1][row] = va.y;
                As[kp + 2][row] = va.z; As[kp + 3][row] = va.w;
                float4 vb = *(const float4*)&g_u[(j0 + row) * K + kc + kp];
                Bs[kp + 0][row] = vb.x; Bs[kp + 1][row] = vb.y;
                Bs[kp + 2][row] = vb.z; Bs[kp + 3][row] = vb.w;
            }
            __syncthreads();
#pragma unroll
            for (int kk = 0; kk < 32; kk++) {
                float4 a0 = *(const float4*)&As[kk][ty * 4];
                float4 b0 = *(const float4*)&Bs[kk][tx * 8];
                float4 b1 = *(const float4*)&Bs[kk][tx * 8 + 4];
                ull av2[4];
                av2[0] = splat2(a0.x); av2[1] = splat2(a0.y);
                av2[2] = splat2(a0.z); av2[3] = splat2(a0.w);
                ull bv[4];
                bv[0] = pack2(b0.x, b0.y); bv[1] = pack2(b0.z, b0.w);
                bv[2] = pack2(b1.x, b1.y); bv[3] = pack2(b1.z, b1.w);
#pragma unroll
                for (int m = 0; m < 4; m++)
#pragma unroll
                    for (int p = 0; p < 4; p++)
                        acc2[m][p] = fma2(av2[m], bv[p], acc2[m][p]);
            }
        }

        float rhi[4], rhj[8];
#pragma unroll
        for (int m = 0; m < 4; m++) rhi[m] = g_rh[i0 + ty * 4 + m];
#pragma unroll
        for (int n = 0; n < 8; n++) rhj[n] = g_rh[j0 + tx * 8 + n];

        float rows[4], cols[8];
#pragma unroll
        for (int m = 0; m < 4; m++) rows[m] = 0.f;
#pragma unroll
        for (int n = 0; n < 8; n++) cols[n] = 0.f;
#pragma unroll
        for (int m = 0; m < 4; m++) {
#pragma unroll
            for (int p = 0; p < 4; p++) {
                float glo, ghi;
                unpack2(acc2[m][p], glo, ghi);
                float e0 = ex2f(glo - rhi[m] - rhj[2 * p + 0]);
                float e1 = ex2f(ghi - rhi[m] - rhj[2 * p + 1]);
                rows[m] += e0 + e1;
                cols[2 * p + 0] += e0;
                cols[2 * p + 1] += e1;
            }
        }

        // row sums: reduce over tx within each 16-lane half-warp
#pragma unroll
        for (int o = 8; o; o >>= 1)
#pragma unroll
            for (int m = 0; m < 4; m++)
                rows[m] += __shfl_xor_sync(0xffffffffu, rows[m], o);
        if (tx == 0) {
#pragma unroll
            for (int m = 0; m < 4; m++)
                atomicAdd(&g_S[i0 + ty * 4 + m], rows[m]);
        }

        // col sums via smem (aliased over As after all reads done)
        __syncthreads();
        float (*colP)[128] = reinterpret_cast<float(*)[128]>(s_buf);
#pragma unroll
        for (int n = 0; n < 8; n++) colP[ty][tx * 8 + n] = cols[n];
        __syncthreads();
        if (ti != tj && tid < 128) {
            float ssum = 0.f;
#pragma unroll
            for (int t = 0; t < 32; t++) ssum += colP[t][tid];
            atomicAdd(&g_S[j0 + tid], ssum);
        }
    }
    grid_bar(2);

    // =========== P3: combine + global reduce ================================
    if (B < 128) {
        float* T_sh = reinterpret_cast<float*>(s_buf);                 // 20 KB
        float* part = T_sh + NMAX * K;                                 // [16*4]
        float* vv   = part + 64;                                       // [16]

        const int k = tid & 127;
        const int g = tid >> 7;
        const int i0 = B * 16;
        const int r0 = i0 + g * 4;

        float a[4];
#pragma unroll
        for (int r = 0; r < 4; r++) a[r] = g_xs[(r0 + r) * K + k];

#pragma unroll
        for (int r = 0; r < 3; r++) {
            int idx = tid + NTHR * r;
            if (idx < (NMAX * K) / 4)
                reinterpret_cast<float4*>(T_sh)[idx] =
                    reinterpret_cast<const float4*>(g_T)[idx];
        }
        __syncthreads();

        float S[4];
        {
            float t = T_sh[(NMAX - 1) * K + k];
#pragma unroll
            for (int r = 0; r < 4; r++) S[r] = t;
        }
#pragma unroll
        for (int n = NMAX - 2; n >= 0; n--) {
            float t = T_sh[n * K + k];
#pragma unroll
            for (int r = 0; r < 4; r++) S[r] = fmaf(S[r], a[r], t);
        }

        float val[4];
#pragma unroll
        for (int r = 0; r < 4; r++)
            val[r] = lnf(S[r]) - 0.5f * a[r] * a[r];

#pragma unroll
        for (int o = 16; o; o >>= 1)
#pragma unroll
            for (int r = 0; r < 4; r++)
                val[r] += __shfl_xor_sync(0xffffffffu, val[r], o);

        const int w = tid >> 5, lane = tid & 31;
        if (lane == 0) {
#pragma unroll
            for (int r = 0; r < 4; r++) part[w * 4 + r] = val[r];
        }
        __syncthreads();
        if (tid < 16) {
            int gg = tid >> 2, rr = tid & 3;
            float tot = part[(gg * 4 + 0) * 4 + rr] + part[(gg * 4 + 1) * 4 + rr]
                      + part[(gg * 4 + 2) * 4 + rr] + part[(gg * 4 + 3) * 4 + rr];
            vv[tid] = logf(g_S[i0 + tid]) - tot;
        }
        __syncthreads();
        if (tid == 0) {
            float bsum = 0.f;
#pragma unroll
            for (int r = 0; r < 16; r++) bsum += vv[r];
            atomicAdd(&g_acc, bsum);
        }
    }

    // final arrival: last block writes the scalar
    __threadfence();
    __syncthreads();
    if (tid == 0) {
        unsigned ticket = atomicAdd(&g_bar[3], 1u);
        if (ticket % NB == (unsigned)(NB - 1)) {
            __threadfence();
            float total = atomicAdd(&g_acc, 0.f);
            out[0] = total / (float)N + (float)(K - 1) * logf((float)N);
        }
    }
}

// ---------------------------------------------------------------------------
extern "C" void kernel_launch(void* const* d_in, const int* in_sizes, int n_in,
                              void* d_out, int out_size) {
    (void)in_sizes; (void)n_in; (void)out_size;
    const float* z = (const float*)d_in[0];
    float* out = (float*)d_out;

    fused_kernel<<<NB, NTHR>>>(z, out);
}

// round 11
// speedup vs baseline: 1.2910x; 1.2910x over previous
#include <cuda_runtime.h>
#include <math.h>

#define N    2048
#define K    128
#define NMAX 40

#define SQL2E 1.2011224087864498f   // sqrt(log2(e))
#define NL2E  -0.7213475204444817f  // -0.5*log2(e)
#define HL2E  0.7213475204444817f   // 0.5*log2(e)
#define LN2f  0.6931471805599453f

typedef unsigned long long ull;

__device__ float g_u  [N * K];
__device__ float g_xs [N * K];
__device__ float g_rh [N];
__device__ float g_S  [N];
__device__ float g_T  [NMAX * K];
__device__ float g_pS [64 * K];
__device__ float g_pQ [64 * K];
__device__ float g_acc;
__device__ unsigned g_cnt;

__device__ __forceinline__ float ex2f(float x) {
    float r; asm("ex2.approx.f32 %0, %1;" : "=f"(r) : "f"(x)); return r;
}
__device__ __forceinline__ float lg2f(float x) {
    float r; asm("lg2.approx.f32 %0, %1;" : "=f"(r) : "f"(x)); return r;
}
__device__ __forceinline__ float lnf(float x) { return lg2f(x) * LN2f; }

__device__ __forceinline__ ull splat2(float x) {
    ull r; asm("mov.b64 %0, {%1, %1};" : "=l"(r) : "f"(x)); return r;
}
__device__ __forceinline__ ull pack2(float lo, float hi) {
    ull r; asm("mov.b64 %0, {%1, %2};" : "=l"(r) : "f"(lo), "f"(hi)); return r;
}
__device__ __forceinline__ ull fma2(ull a, ull b, ull c) {
    ull d; asm("fma.rn.f32x2 %0, %1, %2, %3;" : "=l"(d) : "l"(a), "l"(b), "l"(c)); return d;
}
__device__ __forceinline__ void unpack2(ull v, float& lo, float& hi) {
    asm("mov.b64 {%0, %1}, %2;" : "=f"(lo), "=f"(hi) : "l"(v));
}

// ---------------------------------------------------------------------------
// K1: partial column sums (coalesced) + zero accumulators. 64 blocks x 128.
// ---------------------------------------------------------------------------
__global__ __launch_bounds__(128) void sums_kernel(const float* __restrict__ z) {
    const int k = threadIdx.x;
    const int b = blockIdx.x;
    const int r0 = b * 32;
    float s = 0.f, sq = 0.f;
#pragma unroll 8
    for (int r = 0; r < 32; r++) {
        float v = z[(r0 + r) * K + k];
        s += v; sq += v * v;
    }
    g_pS[b * K + k] = s;
    g_pQ[b * K + k] = sq;

    if (b < NMAX)            g_T[b * 128 + k] = 0.f;           // 40*128
    else if (b < NMAX + 16)  g_S[(b - NMAX) * 128 + k] = 0.f;  // 16*128
    if (b == 0 && k == 0) { g_acc = 0.f; g_cnt = 0u; }
}

// ---------------------------------------------------------------------------
// K2: finalize (redundant) + standardize + moments + row norms.
// 128 blocks x 128 threads; block = 16 rows, thread = column k.
// ---------------------------------------------------------------------------
__global__ __launch_bounds__(128) void standmom_kernel(const float* __restrict__ z) {
    const int k = threadIdx.x;
    const int r0 = blockIdx.x * 16;

    float s = 0.f, sq = 0.f;
#pragma unroll 8
    for (int b = 0; b < 64; b++) {
        s  += g_pS[b * K + k];
        sq += g_pQ[b * K + k];
    }
    const float mean = s / (float)N;
    float var = (sq - s * mean) / (float)(N - 1);
    var = fmaxf(var, 0.f);
    const float rs = 1.f / (sqrtf(var) + 1e-6f);

    float bx[16], q[16], rh16[16];
#pragma unroll
    for (int r = 0; r < 16; r++) {
        int row = r0 + r;
        float xs = (z[row * K + k] - mean) * rs;
        g_xs[row * K + k] = xs;
        g_u [row * K + k] = xs * SQL2E;
        bx[r] = xs;
        q[r]  = ex2f(NL2E * xs * xs);
        rh16[r] = xs * xs;
    }

    float acc[NMAX];
#pragma unroll
    for (int n = 0; n < NMAX; n++) acc[n] = 0.f;
#pragma unroll
    for (int n = 0; n < NMAX; n++) {
        const float rinv = 1.0f / (float)(n + 1);
#pragma unroll
        for (int r = 0; r < 16; r++) {
            acc[n] += q[r];
            q[r] *= bx[r] * rinv;
        }
    }
#pragma unroll
    for (int n = 0; n < NMAX; n++) atomicAdd(&g_T[n * K + k], acc[n]);

#pragma unroll
    for (int o = 16; o; o >>= 1)
#pragma unroll
        for (int r = 0; r < 16; r++)
            rh16[r] += __shfl_xor_sync(0xffffffffu, rh16[r], o);

    __shared__ float shr[4][16];
    const int w = k >> 5, lane = k & 31;
    if (lane == 0) {
#pragma unroll
        for (int r = 0; r < 16; r++) shr[w][r] = rh16[r];
    }
    __syncthreads();
    if (k < 16)
        g_rh[r0 + k] = HL2E * (shr[0][k] + shr[1][k] + shr[2][k] + shr[3][k]);
}

// ---------------------------------------------------------------------------
// K3: symmetric Gram (fma.rn.f32x2) + fused exp + row/col sums.
// 136 blocks x 256 threads, 8x8 microtiles. Unchanged from R7.
// ---------------------------------------------------------------------------
__global__ __launch_bounds__(256) void gram_kernel() {
    __shared__ float As[32][132];
    __shared__ float Bs[32][132];
    __shared__ float colP[16][128];

    const int tid = threadIdx.x;
    const int tx = tid & 15, ty = tid >> 4;

    int rem = blockIdx.x, ti = 0;
    for (int t = 0; t < 16; t++) {
        int L = 16 - t;
        if (rem < L) { ti = t; break; }
        rem -= L;
    }
    const int tj = ti + rem;
    const int i0 = ti * 128, j0 = tj * 128;

    ull acc2[8][4];
#pragma unroll
    for (int m = 0; m < 8; m++)
#pragma unroll
        for (int p = 0; p < 4; p++) acc2[m][p] = splat2(0.f);

#pragma unroll 1
    for (int kc = 0; kc < K; kc += 32) {
        __syncthreads();
#pragma unroll
        for (int r = 0; r < 4; r++) {
            int f = tid + 256 * r;
            int row = f >> 3, kp = (f & 7) * 4;
            float4 va = *(const float4*)&g_u[(i0 + row) * K + kc + kp];
            As[kp + 0][row] = va.x; As[kp + 1][row] = va.y;
            As[kp + 2][row] = va.z; As[kp + 3][row] = va.w;
            float4 vb = *(const float4*)&g_u[(j0 + row) * K + kc + kp];
            Bs[kp + 0][row] = vb.x; Bs[kp + 1][row] = vb.y;
            Bs[kp + 2][row] = vb.z; Bs[kp + 3][row] = vb.w;
        }
        __syncthreads();
#pragma unroll
        for (int kk = 0; kk < 32; kk++) {
            float4 a0 = *(const float4*)&As[kk][ty * 8];
            float4 a1 = *(const float4*)&As[kk][ty * 8 + 4];
            float4 b0 = *(const float4*)&Bs[kk][tx * 8];
            float4 b1 = *(const float4*)&Bs[kk][tx * 8 + 4];
            ull av2[8];
            av2[0] = splat2(a0.x); av2[1] = splat2(a0.y);
            av2[2] = splat2(a0.z); av2[3] = splat2(a0.w);
            av2[4] = splat2(a1.x); av2[5] = splat2(a1.y);
            av2[6] = splat2(a1.z); av2[7] = splat2(a1.w);
            ull bv[4];
            bv[0] = pack2(b0.x, b0.y); bv[1] = pack2(b0.z, b0.w);
            bv[2] = pack2(b1.x, b1.y); bv[3] = pack2(b1.z, b1.w);
#pragma unroll
            for (int m = 0; m < 8; m++)
#pragma unroll
                for (int p = 0; p < 4; p++)
                    acc2[m][p] = fma2(av2[m], bv[p], acc2[m][p]);
        }
    }

    float rhi[8], rhj[8];
#pragma unroll
    for (int m = 0; m < 8; m++) rhi[m] = g_rh[i0 + ty * 8 + m];
#pragma unroll
    for (int n = 0; n < 8; n++) rhj[n] = g_rh[j0 + tx * 8 + n];

    float rows[8], cols[8];
#pragma unroll
    for (int m = 0; m < 8; m++) rows[m] = 0.f;
#pragma unroll
    for (int n = 0; n < 8; n++) cols[n] = 0.f;
#pragma unroll
    for (int m = 0; m < 8; m++) {
#pragma unroll
        for (int p = 0; p < 4; p++) {
            float glo, ghi;
            unpack2(acc2[m][p], glo, ghi);
            float e0 = ex2f(glo - rhi[m] - rhj[2 * p + 0]);
            float e1 = ex2f(ghi - rhi[m] - rhj[2 * p + 1]);
            rows[m] += e0 + e1;
            cols[2 * p + 0] += e0;
            cols[2 * p + 1] += e1;
        }
    }

#pragma unroll
    for (int o = 8; o; o >>= 1)
#pragma unroll
        for (int m = 0; m < 8; m++)
            rows[m] += __shfl_xor_sync(0xffffffffu, rows[m], o);
    if (tx == 0) {
#pragma unroll
        for (int m = 0; m < 8; m++)
            atomicAdd(&g_S[i0 + ty * 8 + m], rows[m]);
    }

#pragma unroll
    for (int n = 0; n < 8; n++) colP[ty][tx * 8 + n] = cols[n];
    __syncthreads();
    if (ti != tj && tid < 128) {
        float ssum = 0.f;
#pragma unroll
        for (int t = 0; t < 16; t++) ssum += colP[t][tid];
        atomicAdd(&g_S[j0 + tid], ssum);
    }
}

// ---------------------------------------------------------------------------
// K4: combine + finish. 128 blocks (ONE wave) x 512 threads; block = 16 rows.
// Thread: k = tid&127, group g = tid>>7 owns 4 rows.
// ---------------------------------------------------------------------------
__global__ __launch_bounds__(512) void combine_kernel(float* __restrict__ out) {
    __shared__ float T_sh[NMAX * K];   // 20 KB
    __shared__ float part[16][4];
    __shared__ float vv[16];
    const int tid = threadIdx.x;
    const int k = tid & 127;
    const int g = tid >> 7;
    const int i0 = blockIdx.x * 16;
    const int r0 = i0 + g * 4;

    // prefetch this thread's xs before the barrier
    float a[4];
#pragma unroll
    for (int r = 0; r < 4; r++) a[r] = g_xs[(r0 + r) * K + k];

    // cooperative coalesced load of T (1280 float4 over 512 threads)
#pragma unroll
    for (int r = 0; r < 3; r++) {
        int idx = tid + 512 * r;
        if (idx < (NMAX * K) / 4)
            reinterpret_cast<float4*>(T_sh)[idx] =
                reinterpret_cast<const float4*>(g_T)[idx];
    }
    __syncthreads();

    float S[4];
    {
        float t = T_sh[(NMAX - 1) * K + k];
#pragma unroll
        for (int r = 0; r < 4; r++) S[r] = t;
    }
#pragma unroll
    for (int n = NMAX - 2; n >= 0; n--) {
        float t = T_sh[n * K + k];
#pragma unroll
        for (int r = 0; r < 4; r++) S[r] = fmaf(S[r], a[r], t);
    }

    float val[4];
#pragma unroll
    for (int r = 0; r < 4; r++)
        val[r] = lnf(S[r]) - 0.5f * a[r] * a[r];

#pragma unroll
    for (int o = 16; o; o >>= 1)
#pragma unroll
        for (int r = 0; r < 4; r++)
            val[r] += __shfl_xor_sync(0xffffffffu, val[r], o);

    const int ww = tid >> 5, lane = tid & 31;
    if (lane == 0) {
#pragma unroll
        for (int r = 0; r < 4; r++) part[ww][r] = val[r];
    }
    __syncthreads();
    if (tid < 16) {
        int gg = tid >> 2, rr = tid & 3;
        float tot = part[gg * 4 + 0][rr] + part[gg * 4 + 1][rr]
                  + part[gg * 4 + 2][rr] + part[gg * 4 + 3][rr];
        vv[tid] = logf(g_S[i0 + tid]) - tot;   // v_i (i = i0 + gg*4 + rr = i0+tid)
    }
    __syncthreads();

    if (tid == 0) {
        float bsum = 0.f;
#pragma unroll
        for (int r = 0; r < 16; r++) bsum += vv[r];
        atomicAdd(&g_acc, bsum);
        __threadfence();
        unsigned old = atomicAdd(&g_cnt, 1u);
        if (old == (unsigned)(gridDim.x - 1)) {
            __threadfence();
            out[0] = g_acc / (float)N + (float)(K - 1) * logf((float)N);
        }
    }
}

// ---------------------------------------------------------------------------
extern "C" void kernel_launch(void* const* d_in, const int* in_sizes, int n_in,
                              void* d_out, int out_size) {
    (void)in_sizes; (void)n_in; (void)out_size;
    const float* z = (const float*)d_in[0];
    float* out = (float*)d_out;

    sums_kernel    <<<64, 128>>>(z);
    standmom_kernel<<<128, 128>>>(z);
    gram_kernel    <<<136, 256>>>();
    combine_kernel <<<128, 512>>>(out);
}